// round 16
// baseline (speedup 1.0000x reference)
#include <cuda_runtime.h>
#include <cuda_fp16.h>

#define NN 100000
#define EE 1600000
#define GG 1024
#define CAP 64

typedef unsigned long long ull;

// -------------------- device scratch --------------------
__device__ uint4 g_Ah[(size_t)NN * 8];       // aggregation output (fp16: 64 halves/node)
__device__ float g_A4[(size_t)NN * 16];      // layer-0 aggregation (fp32, 16-wide)
__device__ uint4 g_B[(size_t)NN * 8];        // raw layer outputs (fp16)
__device__ uint4 g_H[(size_t)NN * 8];        // activated features fp16
__device__ float g_xpad[(size_t)NN * 16];
__device__ int   g_cnt[NN];                  // zero-initialized; re-zeroed by layer-2 gather
__device__ int2  g_epack[(size_t)NN * CAP + 128];
__device__ int   g_goff[GG + 1];
__device__ float g_stats[256];

__device__ __forceinline__ void fma2(ull& d, ull a, ull b) {
    asm("fma.rn.f32x2 %0, %1, %2, %0;" : "+l"(d) : "l"(a), "l"(b));
}
__device__ __forceinline__ float2 unpack2(ull v) {
    float2 r; asm("mov.b64 {%0,%1}, %2;" : "=f"(r.x), "=f"(r.y) : "l"(v)); return r;
}
__device__ __forceinline__ ull pack2(float lo, float hi) {
    ull r; asm("mov.b64 %0, {%1,%2};" : "=l"(r) : "f"(lo), "f"(hi)); return r;
}
__device__ __forceinline__ ull rep2(float v) {
    ull r; asm("mov.b64 %0, {%1,%1};" : "=l"(r) : "f"(v)); return r;
}

// -------------------- fused placement + xpad + graph bounds ---------------------
__global__ void place_prep(const int* __restrict__ src, const int* __restrict__ dst,
                           const float* __restrict__ ew, int* __restrict__ cnt,
                           int2* __restrict__ epack,
                           const float* __restrict__ x, float* __restrict__ xp,
                           const int* __restrict__ batch, int* __restrict__ goff) {
    int e = blockIdx.x * blockDim.x + threadIdx.x;
    if (e < EE) {
        int d = dst[e];
        int p = atomicAdd(&cnt[d], 1);
        epack[((size_t)d << 6) + p] = make_int2(src[e], __float_as_int(ew[e]));
    }
    if (e < NN * 16) { int n = e >> 4, c = e & 15; xp[e] = (c < 9) ? x[n * 9 + c] : 0.f; }
    if (e < NN) {
        int bi = batch[e];
        if (e == 0) { for (int g = 0; g <= bi; g++) goff[g] = 0; }
        else { int bp = batch[e - 1]; for (int g = bp + 1; g <= bi; g++) goff[g] = e; }
        if (e == NN - 1) { for (int g = bi + 1; g <= GG; g++) goff[g] = NN; }
    }
}

// -------------------- layer-0 aggregation (fp32, pipelined unroll-4) ------------
__global__ void __launch_bounds__(256) agg_csr4(
    const float* __restrict__ h, const int* __restrict__ cnt,
    const int2* __restrict__ epack, float* __restrict__ agg, float* __restrict__ stats) {
    if (blockIdx.x == 0) stats[threadIdx.x] = 0.f;
    int node = blockIdx.x * 64 + (threadIdx.x >> 2);
    int lane = threadIdx.x & 3;
    if (node >= NN) return;
    int beg = node << 6, end = beg + cnt[node];
    float4 acc = make_float4(0.f, 0.f, 0.f, 0.f);
    int i = beg;
    if (i + 3 < end) {
        int4 p01 = *(const int4*)&epack[i];
        int4 p23 = *(const int4*)&epack[i + 2];
        for (; i + 7 < end; i += 4) {
            int4 q01 = *(const int4*)&epack[i + 4];
            int4 q23 = *(const int4*)&epack[i + 6];
            float4 v0 = ((const float4*)h)[(size_t)p01.x * 4 + lane];
            float4 v1 = ((const float4*)h)[(size_t)p01.z * 4 + lane];
            float4 v2 = ((const float4*)h)[(size_t)p23.x * 4 + lane];
            float4 v3 = ((const float4*)h)[(size_t)p23.z * 4 + lane];
            float w0 = __int_as_float(p01.y), w1 = __int_as_float(p01.w);
            float w2 = __int_as_float(p23.y), w3 = __int_as_float(p23.w);
            acc.x = fmaf(v0.x, w0, acc.x); acc.y = fmaf(v0.y, w0, acc.y);
            acc.z = fmaf(v0.z, w0, acc.z); acc.w = fmaf(v0.w, w0, acc.w);
            acc.x = fmaf(v1.x, w1, acc.x); acc.y = fmaf(v1.y, w1, acc.y);
            acc.z = fmaf(v1.z, w1, acc.z); acc.w = fmaf(v1.w, w1, acc.w);
            acc.x = fmaf(v2.x, w2, acc.x); acc.y = fmaf(v2.y, w2, acc.y);
            acc.z = fmaf(v2.z, w2, acc.z); acc.w = fmaf(v2.w, w2, acc.w);
            acc.x = fmaf(v3.x, w3, acc.x); acc.y = fmaf(v3.y, w3, acc.y);
            acc.z = fmaf(v3.z, w3, acc.z); acc.w = fmaf(v3.w, w3, acc.w);
            p01 = q01; p23 = q23;
        }
        {
            float4 v0 = ((const float4*)h)[(size_t)p01.x * 4 + lane];
            float4 v1 = ((const float4*)h)[(size_t)p01.z * 4 + lane];
            float4 v2 = ((const float4*)h)[(size_t)p23.x * 4 + lane];
            float4 v3 = ((const float4*)h)[(size_t)p23.z * 4 + lane];
            float w0 = __int_as_float(p01.y), w1 = __int_as_float(p01.w);
            float w2 = __int_as_float(p23.y), w3 = __int_as_float(p23.w);
            acc.x = fmaf(v0.x, w0, acc.x); acc.y = fmaf(v0.y, w0, acc.y);
            acc.z = fmaf(v0.z, w0, acc.z); acc.w = fmaf(v0.w, w0, acc.w);
            acc.x = fmaf(v1.x, w1, acc.x); acc.y = fmaf(v1.y, w1, acc.y);
            acc.z = fmaf(v1.z, w1, acc.z); acc.w = fmaf(v1.w, w1, acc.w);
            acc.x = fmaf(v2.x, w2, acc.x); acc.y = fmaf(v2.y, w2, acc.y);
            acc.z = fmaf(v2.z, w2, acc.z); acc.w = fmaf(v2.w, w2, acc.w);
            acc.x = fmaf(v3.x, w3, acc.x); acc.y = fmaf(v3.y, w3, acc.y);
            acc.z = fmaf(v3.z, w3, acc.z); acc.w = fmaf(v3.w, w3, acc.w);
            i += 4;
        }
    }
    for (; i < end; ++i) {
        int2 ep = epack[i];
        float w = __int_as_float(ep.y);
        float4 v = ((const float4*)h)[(size_t)ep.x * 4 + lane];
        acc.x = fmaf(v.x, w, acc.x); acc.y = fmaf(v.y, w, acc.y);
        acc.z = fmaf(v.z, w, acc.z); acc.w = fmaf(v.w, w, acc.w);
    }
    ((float4*)agg)[(size_t)node * 4 + lane] = acc;
}

// -------------------- fp16 aggregation (pipelined unroll-4, fp16 out) -----------
// ZERO_CNT: last user of cnt re-zeroes it for the next graph replay.
__device__ __forceinline__ void accum8(float* acc, uint4 r, float w) {
    __half2* hp = (__half2*)&r;
#pragma unroll
    for (int j = 0; j < 4; j++) {
        float2 f = __half22float2(hp[j]);
        acc[2 * j]     = fmaf(f.x, w, acc[2 * j]);
        acc[2 * j + 1] = fmaf(f.y, w, acc[2 * j + 1]);
    }
}

template <bool ZERO_CNT>
__global__ void __launch_bounds__(256) agg_csr_h(
    const uint4* __restrict__ h, int* __restrict__ cnt,
    const int2* __restrict__ epack, uint4* __restrict__ aggh) {
    int node = blockIdx.x * 32 + (threadIdx.x >> 3);
    int lane = threadIdx.x & 7;
    if (node >= NN) return;
    int beg = node << 6, end = beg + cnt[node];
    if (ZERO_CNT && lane == 0) cnt[node] = 0;
    float acc[8];
#pragma unroll
    for (int j = 0; j < 8; j++) acc[j] = 0.f;
    int i = beg;
    if (i + 3 < end) {
        int4 p01 = *(const int4*)&epack[i];
        int4 p23 = *(const int4*)&epack[i + 2];
        for (; i + 7 < end; i += 4) {
            int4 q01 = *(const int4*)&epack[i + 4];
            int4 q23 = *(const int4*)&epack[i + 6];
            uint4 r0 = h[(size_t)p01.x * 8 + lane];
            uint4 r1 = h[(size_t)p01.z * 8 + lane];
            uint4 r2 = h[(size_t)p23.x * 8 + lane];
            uint4 r3 = h[(size_t)p23.z * 8 + lane];
            accum8(acc, r0, __int_as_float(p01.y));
            accum8(acc, r1, __int_as_float(p01.w));
            accum8(acc, r2, __int_as_float(p23.y));
            accum8(acc, r3, __int_as_float(p23.w));
            p01 = q01; p23 = q23;
        }
        {
            uint4 r0 = h[(size_t)p01.x * 8 + lane];
            uint4 r1 = h[(size_t)p01.z * 8 + lane];
            uint4 r2 = h[(size_t)p23.x * 8 + lane];
            uint4 r3 = h[(size_t)p23.z * 8 + lane];
            accum8(acc, r0, __int_as_float(p01.y));
            accum8(acc, r1, __int_as_float(p01.w));
            accum8(acc, r2, __int_as_float(p23.y));
            accum8(acc, r3, __int_as_float(p23.w));
            i += 4;
        }
    }
    for (; i < end; ++i) {
        int2 e0 = epack[i];
        uint4 r0 = h[(size_t)e0.x * 8 + lane];
        accum8(acc, r0, __int_as_float(e0.y));
    }
    __half2 o0 = __floats2half2_rn(acc[0], acc[1]);
    __half2 o1 = __floats2half2_rn(acc[2], acc[3]);
    __half2 o2 = __floats2half2_rn(acc[4], acc[5]);
    __half2 o3 = __floats2half2_rn(acc[6], acc[7]);
    uint4 o;
    o.x = *(unsigned*)&o0; o.y = *(unsigned*)&o1;
    o.z = *(unsigned*)&o2; o.w = *(unsigned*)&o3;
    aggh[(size_t)node * 8 + lane] = o;
}

// -------------------- layer-0 node update (K=9, f32x2 feature pairs, fp16 out) --
__global__ void __launch_bounds__(128) node_update9(
    const float* __restrict__ Ag, const float* __restrict__ Xin,
    const float* __restrict__ Wrel, const float* __restrict__ Wroot,
    const float* __restrict__ bias, uint4* __restrict__ Outh, float* stats) {
    constexpr int K = 9, PAD = 18;
    extern __shared__ float sm[];
    float* sA   = sm;
    float* sX   = sA + 64 * PAD;
    float* sWr  = sX + 64 * PAD;
    float* sWo  = sWr + K * 64;
    float* sSum = sWo + K * 64;
    float* sSq  = sSum + 64;

    const int tid = threadIdx.x;
    const int base = blockIdx.x * 64;

    for (int i = tid; i < K * 16; i += 128) {
        ((float4*)sWr)[i] = ((const float4*)Wrel)[i];
        ((float4*)sWo)[i] = ((const float4*)Wroot)[i];
    }
    for (int i = tid; i < 64 * 4; i += 128) {
        int r = i >> 2, c = i & 3;
        int n = base + r;
        float4 va = make_float4(0.f, 0.f, 0.f, 0.f), vx = va;
        if (n < NN) {
            va = *(const float4*)&Ag[(size_t)n * 16 + c * 4];
            vx = *(const float4*)&Xin[(size_t)n * 16 + c * 4];
        }
        ull* pa = (ull*)&sA[r * PAD + c * 4];
        ull* px = (ull*)&sX[r * PAD + c * 4];
        pa[0] = pack2(va.x, va.y); pa[1] = pack2(va.z, va.w);
        px[0] = pack2(vx.x, vx.y); px[1] = pack2(vx.z, vx.w);
    }
    if (tid < 64) { sSum[tid] = 0.f; sSq[tid] = 0.f; }
    __syncthreads();

    const int f0 = (tid & 7) * 8;
    const int ng = (tid >> 3) * 4;

    ull acc2[4][4];
#pragma unroll
    for (int i = 0; i < 4; i++)
#pragma unroll
        for (int p = 0; p < 4; p++) acc2[i][p] = 0ull;

#pragma unroll
    for (int k = 0; k < K; ++k) {
        ull ra[4], rx[4];
#pragma unroll
        for (int i = 0; i < 4; i++) {
            ra[i] = rep2(sA[(ng + i) * PAD + k]);
            rx[i] = rep2(sX[(ng + i) * PAD + k]);
        }
        ulonglong2 wr0 = *(const ulonglong2*)&sWr[k * 64 + f0];
        ulonglong2 wr1 = *(const ulonglong2*)&sWr[k * 64 + f0 + 4];
        ulonglong2 wo0 = *(const ulonglong2*)&sWo[k * 64 + f0];
        ulonglong2 wo1 = *(const ulonglong2*)&sWo[k * 64 + f0 + 4];
#pragma unroll
        for (int i = 0; i < 4; i++) {
            fma2(acc2[i][0], ra[i], wr0.x);
            fma2(acc2[i][1], ra[i], wr0.y);
            fma2(acc2[i][2], ra[i], wr1.x);
            fma2(acc2[i][3], ra[i], wr1.y);
            fma2(acc2[i][0], rx[i], wo0.x);
            fma2(acc2[i][1], rx[i], wo0.y);
            fma2(acc2[i][2], rx[i], wo1.x);
            fma2(acc2[i][3], rx[i], wo1.y);
        }
    }

    float bz[8];
    *(float4*)&bz[0] = *(const float4*)&bias[f0];
    *(float4*)&bz[4] = *(const float4*)&bias[f0 + 4];

    float s[8], q[8];
#pragma unroll
    for (int j = 0; j < 8; j++) { s[j] = 0.f; q[j] = 0.f; }

#pragma unroll
    for (int i = 0; i < 4; i++) {
        int n = base + ng + i;
        if (n < NN) {
            float o[8];
#pragma unroll
            for (int p = 0; p < 4; p++) {
                float2 v = unpack2(acc2[i][p]);
                o[2 * p]     = v.x + bz[2 * p];
                o[2 * p + 1] = v.y + bz[2 * p + 1];
            }
            __half2 h0 = __floats2half2_rn(o[0], o[1]);
            __half2 h1 = __floats2half2_rn(o[2], o[3]);
            __half2 h2 = __floats2half2_rn(o[4], o[5]);
            __half2 h3 = __floats2half2_rn(o[6], o[7]);
            uint4 ov;
            ov.x = *(unsigned*)&h0; ov.y = *(unsigned*)&h1;
            ov.z = *(unsigned*)&h2; ov.w = *(unsigned*)&h3;
            Outh[(size_t)n * 8 + (tid & 7)] = ov;
#pragma unroll
            for (int j = 0; j < 8; j++) { s[j] += o[j]; q[j] += o[j] * o[j]; }
        }
    }
#pragma unroll
    for (int j = 0; j < 8; j++) {
        atomicAdd(&sSum[f0 + j], s[j]);
        atomicAdd(&sSq[f0 + j], q[j]);
    }
    __syncthreads();
    if (tid < 64) {
        atomicAdd(&stats[tid], sSum[tid]);
        atomicAdd(&stats[64 + tid], sSq[tid]);
    }
}

// -------------------- f32x2 node update (K=64), fp16 Ag + Xin, fp16 out ---------
__global__ void __launch_bounds__(128) node_update64(
    const uint4* __restrict__ Agh, const uint4* __restrict__ Xh,
    const float* __restrict__ Wrel, const float* __restrict__ Wroot,
    const float* __restrict__ bias, __half* __restrict__ Outh, float* stats) {
    constexpr int PAD = 66;
    extern __shared__ float sm[];
    float* sA   = sm;
    float* sX   = sA + 64 * PAD;
    ull*   sWr  = (ull*)(sX + 64 * PAD);
    ull*   sWo  = sWr + 32 * 64;
    float* sSum = (float*)(sWo + 32 * 64);
    float* sSq  = sSum + 64;

    const int tid = threadIdx.x;
    const int base = blockIdx.x * 64;

    for (int idx = tid; idx < 32 * 16; idx += 128) {
        int k2 = idx >> 4, c4 = idx & 15;
        float4 r0 = ((const float4*)Wrel)[(2 * k2) * 16 + c4];
        float4 r1 = ((const float4*)Wrel)[(2 * k2 + 1) * 16 + c4];
        ull* p = &sWr[k2 * 64 + c4 * 4];
        p[0] = pack2(r0.x, r1.x); p[1] = pack2(r0.y, r1.y);
        p[2] = pack2(r0.z, r1.z); p[3] = pack2(r0.w, r1.w);
        r0 = ((const float4*)Wroot)[(2 * k2) * 16 + c4];
        r1 = ((const float4*)Wroot)[(2 * k2 + 1) * 16 + c4];
        p = &sWo[k2 * 64 + c4 * 4];
        p[0] = pack2(r0.x, r1.x); p[1] = pack2(r0.y, r1.y);
        p[2] = pack2(r0.z, r1.z); p[3] = pack2(r0.w, r1.w);
    }
    for (int i = tid; i < 64 * 8; i += 128) {
        int r = i >> 3, c = i & 7;
        int n = base + r;
        uint4 va = make_uint4(0u, 0u, 0u, 0u), vx = va;
        if (n < NN) {
            va = Agh[(size_t)n * 8 + c];
            vx = Xh[(size_t)n * 8 + c];
        }
        __half2* hpa = (__half2*)&va;
        __half2* hpx = (__half2*)&vx;
        float* oa = &sA[r * PAD + c * 8];
        float* ox = &sX[r * PAD + c * 8];
#pragma unroll
        for (int j = 0; j < 4; j++) {
            float2 fa = __half22float2(hpa[j]);
            float2 fx = __half22float2(hpx[j]);
            oa[2 * j] = fa.x; oa[2 * j + 1] = fa.y;
            ox[2 * j] = fx.x; ox[2 * j + 1] = fx.y;
        }
    }
    if (tid < 64) { sSum[tid] = 0.f; sSq[tid] = 0.f; }
    __syncthreads();

    const int f0 = (tid & 7) * 2;
    const int ng = (tid >> 3) * 4;

    ull acc2[4][8];
#pragma unroll
    for (int i = 0; i < 4; i++)
#pragma unroll
        for (int j = 0; j < 8; j++) acc2[i][j] = 0ull;

#pragma unroll 2
    for (int k2 = 0; k2 < 32; ++k2) {
        ull av[4], xv[4];
#pragma unroll
        for (int i = 0; i < 4; i++) {
            av[i] = *(const ull*)&sA[(ng + i) * PAD + 2 * k2];
            xv[i] = *(const ull*)&sX[(ng + i) * PAD + 2 * k2];
        }
#pragma unroll
        for (int c = 0; c < 4; c++) {
            ulonglong2 wr = *(const ulonglong2*)&sWr[k2 * 64 + f0 + 16 * c];
            ulonglong2 wo = *(const ulonglong2*)&sWo[k2 * 64 + f0 + 16 * c];
#pragma unroll
            for (int i = 0; i < 4; i++) {
                fma2(acc2[i][2 * c],     av[i], wr.x);
                fma2(acc2[i][2 * c + 1], av[i], wr.y);
                fma2(acc2[i][2 * c],     xv[i], wo.x);
                fma2(acc2[i][2 * c + 1], xv[i], wo.y);
            }
        }
    }

    float bz[8];
#pragma unroll
    for (int c = 0; c < 4; c++) {
        float2 b2 = *(const float2*)&bias[f0 + 16 * c];
        bz[2 * c] = b2.x; bz[2 * c + 1] = b2.y;
    }

    float s[8], q[8];
#pragma unroll
    for (int j = 0; j < 8; j++) { s[j] = 0.f; q[j] = 0.f; }

#pragma unroll
    for (int i = 0; i < 4; i++) {
        int n = base + ng + i;
        if (n < NN) {
#pragma unroll
            for (int c = 0; c < 4; c++) {
                float2 e0 = unpack2(acc2[i][2 * c]);
                float2 e1 = unpack2(acc2[i][2 * c + 1]);
                float o0 = e0.x + e0.y + bz[2 * c];
                float o1 = e1.x + e1.y + bz[2 * c + 1];
                __half2 hv = __floats2half2_rn(o0, o1);
                *(__half2*)&Outh[(size_t)n * 64 + f0 + 16 * c] = hv;
                s[2 * c] += o0; q[2 * c] += o0 * o0;
                s[2 * c + 1] += o1; q[2 * c + 1] += o1 * o1;
            }
        }
    }
#pragma unroll
    for (int c = 0; c < 4; c++) {
        atomicAdd(&sSum[f0 + 16 * c],     s[2 * c]);
        atomicAdd(&sSum[f0 + 16 * c + 1], s[2 * c + 1]);
        atomicAdd(&sSq[f0 + 16 * c],      q[2 * c]);
        atomicAdd(&sSq[f0 + 16 * c + 1],  q[2 * c + 1]);
    }
    __syncthreads();
    if (tid < 64) {
        atomicAdd(&stats[tid], sSum[tid]);
        atomicAdd(&stats[64 + tid], sSq[tid]);
    }
}

// -------------------- BN finalize + apply + ReLU (half2 arithmetic) -------------
__global__ void __launch_bounds__(256) bn_act_h(
    const uint4* __restrict__ inh, const float* __restrict__ stats,
    const float* __restrict__ g, const float* __restrict__ be,
    uint4* __restrict__ outh) {
    __shared__ __half2 sc2[32], sh2[32];
    if (threadIdx.x < 32) {
        int f = threadIdx.x * 2;
        const float inv = 1.f / (float)NN;
        float m0 = stats[f] * inv, m1 = stats[f + 1] * inv;
        float v0 = stats[64 + f] * inv - m0 * m0;
        float v1 = stats[64 + f + 1] * inv - m1 * m1;
        float s0 = g[f] * rsqrtf(v0 + 1e-5f);
        float s1 = g[f + 1] * rsqrtf(v1 + 1e-5f);
        sc2[threadIdx.x] = __floats2half2_rn(s0, s1);
        sh2[threadIdx.x] = __floats2half2_rn(fmaf(-m0, s0, be[f]), fmaf(-m1, s1, be[f + 1]));
    }
    __syncthreads();
    int i = blockIdx.x * blockDim.x + threadIdx.x;
    if (i >= NN * 8) return;
    int c4 = (i & 7) * 4;
    uint4 v = inh[i];
    __half2* hp = (__half2*)&v;
    const __half2 z2 = __float2half2_rn(0.f);
#pragma unroll
    for (int j = 0; j < 4; j++)
        hp[j] = __hmax2(__hfma2(hp[j], sc2[c4 + j], sh2[c4 + j]), z2);
    outh[i] = v;
}

// -------------------- layer-2 pooled GEMM + MLP head (128 threads) --------------
__global__ void __launch_bounds__(128) pool2_head(
    const uint4* __restrict__ Agh, const uint4* __restrict__ Xh,
    const float* __restrict__ W2rel, const float* __restrict__ W2root,
    const float* __restrict__ b2, const int* __restrict__ goff,
    const float* __restrict__ Wl1, const float* __restrict__ bl1,
    const float* __restrict__ Wl2, const float* __restrict__ bl2,
    float* __restrict__ out) {
    __shared__ float sAg[2][64], sXp[2][64], sPool[64], sz[64];
    int g = blockIdx.x, t = threadIdx.x;
    int half = t >> 6, f = t & 63;
    int beg = goff[g], end = goff[g + 1];
    const __half* ah = (const __half*)Agh;
    const __half* xh = (const __half*)Xh;
    float sa = 0.f, sx = 0.f;
    for (int n = beg + half; n < end; n += 2) {
        sa += __half2float(ah[(size_t)n * 64 + f]);
        sx += __half2float(xh[(size_t)n * 64 + f]);
    }
    sAg[half][f] = sa; sXp[half][f] = sx;
    __syncthreads();
    if (t < 64) {
        float cnt = (float)(end - beg);
        float acc = cnt * b2[t];
#pragma unroll 8
        for (int k = 0; k < 64; k++) {
            float A = sAg[0][k] + sAg[1][k];
            float X = sXp[0][k] + sXp[1][k];
            acc += A * W2rel[k * 64 + t] + X * W2root[k * 64 + t];
        }
        sPool[t] = acc / fmaxf(cnt, 1.f);
    }
    __syncthreads();
    if (t < 64) {
        float z = bl1[t];
#pragma unroll 8
        for (int k = 0; k < 64; k++) z = fmaf(sPool[k], Wl1[k * 64 + t], z);
        sz[t] = fmaxf(z, 0.f);
    }
    __syncthreads();
    if (t < 6) {
        float o = bl2[t];
#pragma unroll 8
        for (int k = 0; k < 64; k++) o = fmaf(sz[k], Wl2[k * 6 + t], o);
        out[g * 6 + t] = o;
    }
}

// -------------------- launch --------------------
extern "C" void kernel_launch(void* const* d_in, const int* in_sizes, int n_in,
                              void* d_out, int out_size) {
    const float* x     = (const float*)d_in[0];
    const int*   ei    = (const int*)d_in[1];
    const float* ew    = (const float*)d_in[2];
    const int*   batch = (const int*)d_in[3];
    const float *Wrel0 = (const float*)d_in[4],  *Wroot0 = (const float*)d_in[5],  *b0 = (const float*)d_in[6];
    const float *Wrel1 = (const float*)d_in[7],  *Wroot1 = (const float*)d_in[8],  *b1 = (const float*)d_in[9];
    const float *Wrel2 = (const float*)d_in[10], *Wroot2 = (const float*)d_in[11], *b2 = (const float*)d_in[12];
    const float *g0 = (const float*)d_in[13], *be0 = (const float*)d_in[14];
    const float *g1 = (const float*)d_in[15], *be1 = (const float*)d_in[16];
    const float *Wl1 = (const float*)d_in[17], *bl1 = (const float*)d_in[18];
    const float *Wl2 = (const float*)d_in[19], *bl2 = (const float*)d_in[20];
    float* out = (float*)d_out;

    const int* src = ei;
    const int* dst = ei + EE;

    float *pA4, *pX, *pStats;
    uint4 *pAh, *pB, *pH;
    int *pCnt, *pGoff;
    int2* pEpack;
    cudaGetSymbolAddress((void**)&pAh, g_Ah);
    cudaGetSymbolAddress((void**)&pA4, g_A4);
    cudaGetSymbolAddress((void**)&pB, g_B);
    cudaGetSymbolAddress((void**)&pH, g_H);
    cudaGetSymbolAddress((void**)&pX, g_xpad);
    cudaGetSymbolAddress((void**)&pStats, g_stats);
    cudaGetSymbolAddress((void**)&pCnt, g_cnt);
    cudaGetSymbolAddress((void**)&pGoff, g_goff);
    cudaGetSymbolAddress((void**)&pEpack, g_epack);

    const int smem64 = 64 * 66 * 4 * 2 + 32 * 64 * 8 * 2 + 128 * 4;       // 67072 B
    const int smem9  = (64 * 18 * 2 + 9 * 64 * 2 + 128) * (int)sizeof(float);  // 14336 B
    cudaFuncSetAttribute((const void*)node_update64,
                         cudaFuncAttributeMaxDynamicSharedMemorySize, smem64);

    const int NB = (NN + 63) / 64;

    // ---- slotted CSR build + prep (cnt re-zeroed by layer-2 gather; no memset) --
    place_prep<<<(EE + 511) / 512, 512>>>(src, dst, ew, pCnt, pEpack, x, pX, batch, pGoff);

    // ---- layer 0 ----
    agg_csr4<<<(NN + 63) / 64, 256>>>(pX, pCnt, pEpack, pA4, pStats);
    node_update9<<<NB, 128, smem9>>>(pA4, pX, Wrel0, Wroot0, b0, pB, pStats);
    bn_act_h<<<(NN * 8 + 255) / 256, 256>>>(pB, pStats, g0, be0, pH);

    // ---- layer 1 ----
    agg_csr_h<false><<<(NN + 31) / 32, 256>>>(pH, pCnt, pEpack, pAh);
    node_update64<<<NB, 128, smem64>>>(pAh, pH, Wrel1, Wroot1, b1, (__half*)pB, pStats + 128);
    bn_act_h<<<(NN * 8 + 255) / 256, 256>>>(pB, pStats + 128, g1, be1, pH);

    // ---- layer 2 (gather re-zeroes cnt for next replay) ----
    agg_csr_h<true><<<(NN + 31) / 32, 256>>>(pH, pCnt, pEpack, pAh);
    pool2_head<<<GG, 128>>>(pAh, pH, Wrel2, Wroot2, b2, pGoff, Wl1, bl1, Wl2, bl2, out);
}

// round 17
// speedup vs baseline: 1.0610x; 1.0610x over previous
#include <cuda_runtime.h>
#include <cuda_fp16.h>

#define NN 100000
#define EE 1600000
#define GG 1024
#define CAP 64

typedef unsigned long long ull;

// -------------------- device scratch --------------------
__device__ uint4 g_Ah[(size_t)NN * 8];       // aggregation output (fp16: 64 halves/node)
__device__ float g_A4[(size_t)NN * 16];      // layer-0 aggregation (fp32, 16-wide)
__device__ uint4 g_B[(size_t)NN * 8];        // raw layer outputs (fp16)
__device__ uint4 g_H[(size_t)NN * 8];        // activated features fp16
__device__ uint4 g_xh[(size_t)NN * 2];       // padded input as fp16 (16 halves/node)
__device__ int   g_cnt[NN];
__device__ int2  g_epack[(size_t)NN * CAP + 128];
__device__ int   g_goff[GG + 1];
__device__ float g_stats[256];

__device__ __forceinline__ void fma2(ull& d, ull a, ull b) {
    asm("fma.rn.f32x2 %0, %1, %2, %0;" : "+l"(d) : "l"(a), "l"(b));
}
__device__ __forceinline__ float2 unpack2(ull v) {
    float2 r; asm("mov.b64 {%0,%1}, %2;" : "=f"(r.x), "=f"(r.y) : "l"(v)); return r;
}
__device__ __forceinline__ ull pack2(float lo, float hi) {
    ull r; asm("mov.b64 %0, {%1,%2};" : "=l"(r) : "f"(lo), "f"(hi)); return r;
}
__device__ __forceinline__ ull rep2(float v) {
    ull r; asm("mov.b64 %0, {%1,%1};" : "=l"(r) : "f"(v)); return r;
}
__device__ __forceinline__ void accum8(float* acc, uint4 r, float w) {
    __half2* hp = (__half2*)&r;
#pragma unroll
    for (int j = 0; j < 4; j++) {
        float2 f = __half22float2(hp[j]);
        acc[2 * j]     = fmaf(f.x, w, acc[2 * j]);
        acc[2 * j + 1] = fmaf(f.y, w, acc[2 * j + 1]);
    }
}

// -------------------- fused placement + fp16 xpad + graph bounds ----------------
__global__ void place_prep(const int* __restrict__ src, const int* __restrict__ dst,
                           const float* __restrict__ ew, int* __restrict__ cnt,
                           int2* __restrict__ epack,
                           const float* __restrict__ x, uint4* __restrict__ xh,
                           const int* __restrict__ batch, int* __restrict__ goff) {
    int e = blockIdx.x * blockDim.x + threadIdx.x;
    if (e < EE) {
        int d = dst[e];
        int p = atomicAdd(&cnt[d], 1);
        epack[((size_t)d << 6) + p] = make_int2(src[e], __float_as_int(ew[e]));
    }
    if (e < NN * 2) {   // one uint4 (8 halves) of padded input per thread
        int n = e >> 1, c0 = (e & 1) * 8;
        __half hv[8];
#pragma unroll
        for (int j = 0; j < 8; j++) {
            int c = c0 + j;
            hv[j] = __float2half_rn((c < 9) ? x[n * 9 + c] : 0.f);
        }
        xh[e] = *(uint4*)hv;
    }
    if (e < NN) {
        int bi = batch[e];
        if (e == 0) { for (int g = 0; g <= bi; g++) goff[g] = 0; }
        else { int bp = batch[e - 1]; for (int g = bp + 1; g <= bi; g++) goff[g] = e; }
        if (e == NN - 1) { for (int g = bi + 1; g <= GG; g++) goff[g] = NN; }
    }
}

// -------------------- layer-0 aggregation (fp16 rows, 2 lanes/node) -------------
__global__ void __launch_bounds__(256) agg_csr4h(
    const uint4* __restrict__ h, const int* __restrict__ cnt,
    const int2* __restrict__ epack, float* __restrict__ agg, float* __restrict__ stats) {
    if (blockIdx.x == 0) stats[threadIdx.x] = 0.f;
    int node = blockIdx.x * 128 + (threadIdx.x >> 1);
    int lane = threadIdx.x & 1;
    if (node >= NN) return;
    int beg = node << 6, end = beg + cnt[node];
    float acc[8];
#pragma unroll
    for (int j = 0; j < 8; j++) acc[j] = 0.f;
    int i = beg;
    if (i + 3 < end) {
        int4 p01 = *(const int4*)&epack[i];
        int4 p23 = *(const int4*)&epack[i + 2];
        for (; i + 7 < end; i += 4) {
            int4 q01 = *(const int4*)&epack[i + 4];
            int4 q23 = *(const int4*)&epack[i + 6];
            uint4 r0 = h[(size_t)p01.x * 2 + lane];
            uint4 r1 = h[(size_t)p01.z * 2 + lane];
            uint4 r2 = h[(size_t)p23.x * 2 + lane];
            uint4 r3 = h[(size_t)p23.z * 2 + lane];
            accum8(acc, r0, __int_as_float(p01.y));
            accum8(acc, r1, __int_as_float(p01.w));
            accum8(acc, r2, __int_as_float(p23.y));
            accum8(acc, r3, __int_as_float(p23.w));
            p01 = q01; p23 = q23;
        }
        {
            uint4 r0 = h[(size_t)p01.x * 2 + lane];
            uint4 r1 = h[(size_t)p01.z * 2 + lane];
            uint4 r2 = h[(size_t)p23.x * 2 + lane];
            uint4 r3 = h[(size_t)p23.z * 2 + lane];
            accum8(acc, r0, __int_as_float(p01.y));
            accum8(acc, r1, __int_as_float(p01.w));
            accum8(acc, r2, __int_as_float(p23.y));
            accum8(acc, r3, __int_as_float(p23.w));
            i += 4;
        }
    }
    for (; i < end; ++i) {
        int2 e0 = epack[i];
        uint4 r0 = h[(size_t)e0.x * 2 + lane];
        accum8(acc, r0, __int_as_float(e0.y));
    }
    float* dstp = &agg[(size_t)node * 16 + lane * 8];
    *(float4*)dstp       = make_float4(acc[0], acc[1], acc[2], acc[3]);
    *(float4*)(dstp + 4) = make_float4(acc[4], acc[5], acc[6], acc[7]);
}

// -------------------- fp16 aggregation (pipelined unroll-4, fp16 out) -----------
__global__ void __launch_bounds__(256) agg_csr_h(
    const uint4* __restrict__ h, const int* __restrict__ cnt,
    const int2* __restrict__ epack, uint4* __restrict__ aggh) {
    int node = blockIdx.x * 32 + (threadIdx.x >> 3);
    int lane = threadIdx.x & 7;
    if (node >= NN) return;
    int beg = node << 6, end = beg + cnt[node];
    float acc[8];
#pragma unroll
    for (int j = 0; j < 8; j++) acc[j] = 0.f;
    int i = beg;
    if (i + 3 < end) {
        int4 p01 = *(const int4*)&epack[i];
        int4 p23 = *(const int4*)&epack[i + 2];
        for (; i + 7 < end; i += 4) {
            int4 q01 = *(const int4*)&epack[i + 4];
            int4 q23 = *(const int4*)&epack[i + 6];
            uint4 r0 = h[(size_t)p01.x * 8 + lane];
            uint4 r1 = h[(size_t)p01.z * 8 + lane];
            uint4 r2 = h[(size_t)p23.x * 8 + lane];
            uint4 r3 = h[(size_t)p23.z * 8 + lane];
            accum8(acc, r0, __int_as_float(p01.y));
            accum8(acc, r1, __int_as_float(p01.w));
            accum8(acc, r2, __int_as_float(p23.y));
            accum8(acc, r3, __int_as_float(p23.w));
            p01 = q01; p23 = q23;
        }
        {
            uint4 r0 = h[(size_t)p01.x * 8 + lane];
            uint4 r1 = h[(size_t)p01.z * 8 + lane];
            uint4 r2 = h[(size_t)p23.x * 8 + lane];
            uint4 r3 = h[(size_t)p23.z * 8 + lane];
            accum8(acc, r0, __int_as_float(p01.y));
            accum8(acc, r1, __int_as_float(p01.w));
            accum8(acc, r2, __int_as_float(p23.y));
            accum8(acc, r3, __int_as_float(p23.w));
            i += 4;
        }
    }
    for (; i < end; ++i) {
        int2 e0 = epack[i];
        uint4 r0 = h[(size_t)e0.x * 8 + lane];
        accum8(acc, r0, __int_as_float(e0.y));
    }
    __half2 o0 = __floats2half2_rn(acc[0], acc[1]);
    __half2 o1 = __floats2half2_rn(acc[2], acc[3]);
    __half2 o2 = __floats2half2_rn(acc[4], acc[5]);
    __half2 o3 = __floats2half2_rn(acc[6], acc[7]);
    uint4 o;
    o.x = *(unsigned*)&o0; o.y = *(unsigned*)&o1;
    o.z = *(unsigned*)&o2; o.w = *(unsigned*)&o3;
    aggh[(size_t)node * 8 + lane] = o;
}

// -------------------- layer-0 node update (K=9, f32x2 pairs, fp16 Xin/out) ------
__global__ void __launch_bounds__(128) node_update9(
    const float* __restrict__ Ag, const uint4* __restrict__ Xh,
    const float* __restrict__ Wrel, const float* __restrict__ Wroot,
    const float* __restrict__ bias, uint4* __restrict__ Outh, float* stats) {
    constexpr int K = 9, PAD = 18;
    extern __shared__ float sm[];
    float* sA   = sm;
    float* sX   = sA + 64 * PAD;
    float* sWr  = sX + 64 * PAD;
    float* sWo  = sWr + K * 64;
    float* sSum = sWo + K * 64;
    float* sSq  = sSum + 64;

    const int tid = threadIdx.x;
    const int base = blockIdx.x * 64;

    for (int i = tid; i < K * 16; i += 128) {
        ((float4*)sWr)[i] = ((const float4*)Wrel)[i];
        ((float4*)sWo)[i] = ((const float4*)Wroot)[i];
    }
    for (int i = tid; i < 64 * 4; i += 128) {   // Ag fp32
        int r = i >> 2, c = i & 3;
        int n = base + r;
        float4 va = make_float4(0.f, 0.f, 0.f, 0.f);
        if (n < NN) va = *(const float4*)&Ag[(size_t)n * 16 + c * 4];
        ull* pa = (ull*)&sA[r * PAD + c * 4];
        pa[0] = pack2(va.x, va.y); pa[1] = pack2(va.z, va.w);
    }
    for (int i = tid; i < 64 * 2; i += 128) {   // Xin fp16
        int r = i >> 1, c = i & 1;
        int n = base + r;
        uint4 v = make_uint4(0u, 0u, 0u, 0u);
        if (n < NN) v = Xh[(size_t)n * 2 + c];
        __half2* hp = (__half2*)&v;
        float* o = &sX[r * PAD + c * 8];
#pragma unroll
        for (int j = 0; j < 4; j++) {
            float2 f = __half22float2(hp[j]);
            o[2 * j] = f.x; o[2 * j + 1] = f.y;
        }
    }
    if (tid < 64) { sSum[tid] = 0.f; sSq[tid] = 0.f; }
    __syncthreads();

    const int f0 = (tid & 7) * 8;
    const int ng = (tid >> 3) * 4;

    ull acc2[4][4];
#pragma unroll
    for (int i = 0; i < 4; i++)
#pragma unroll
        for (int p = 0; p < 4; p++) acc2[i][p] = 0ull;

#pragma unroll
    for (int k = 0; k < K; ++k) {
        ull ra[4], rx[4];
#pragma unroll
        for (int i = 0; i < 4; i++) {
            ra[i] = rep2(sA[(ng + i) * PAD + k]);
            rx[i] = rep2(sX[(ng + i) * PAD + k]);
        }
        ulonglong2 wr0 = *(const ulonglong2*)&sWr[k * 64 + f0];
        ulonglong2 wr1 = *(const ulonglong2*)&sWr[k * 64 + f0 + 4];
        ulonglong2 wo0 = *(const ulonglong2*)&sWo[k * 64 + f0];
        ulonglong2 wo1 = *(const ulonglong2*)&sWo[k * 64 + f0 + 4];
#pragma unroll
        for (int i = 0; i < 4; i++) {
            fma2(acc2[i][0], ra[i], wr0.x);
            fma2(acc2[i][1], ra[i], wr0.y);
            fma2(acc2[i][2], ra[i], wr1.x);
            fma2(acc2[i][3], ra[i], wr1.y);
            fma2(acc2[i][0], rx[i], wo0.x);
            fma2(acc2[i][1], rx[i], wo0.y);
            fma2(acc2[i][2], rx[i], wo1.x);
            fma2(acc2[i][3], rx[i], wo1.y);
        }
    }

    float bz[8];
    *(float4*)&bz[0] = *(const float4*)&bias[f0];
    *(float4*)&bz[4] = *(const float4*)&bias[f0 + 4];

    float s[8], q[8];
#pragma unroll
    for (int j = 0; j < 8; j++) { s[j] = 0.f; q[j] = 0.f; }

#pragma unroll
    for (int i = 0; i < 4; i++) {
        int n = base + ng + i;
        if (n < NN) {
            float o[8];
#pragma unroll
            for (int p = 0; p < 4; p++) {
                float2 v = unpack2(acc2[i][p]);
                o[2 * p]     = v.x + bz[2 * p];
                o[2 * p + 1] = v.y + bz[2 * p + 1];
            }
            __half2 h0 = __floats2half2_rn(o[0], o[1]);
            __half2 h1 = __floats2half2_rn(o[2], o[3]);
            __half2 h2 = __floats2half2_rn(o[4], o[5]);
            __half2 h3 = __floats2half2_rn(o[6], o[7]);
            uint4 ov;
            ov.x = *(unsigned*)&h0; ov.y = *(unsigned*)&h1;
            ov.z = *(unsigned*)&h2; ov.w = *(unsigned*)&h3;
            Outh[(size_t)n * 8 + (tid & 7)] = ov;
#pragma unroll
            for (int j = 0; j < 8; j++) { s[j] += o[j]; q[j] += o[j] * o[j]; }
        }
    }
#pragma unroll
    for (int j = 0; j < 8; j++) {
        atomicAdd(&sSum[f0 + j], s[j]);
        atomicAdd(&sSq[f0 + j], q[j]);
    }
    __syncthreads();
    if (tid < 64) {
        atomicAdd(&stats[tid], sSum[tid]);
        atomicAdd(&stats[64 + tid], sSq[tid]);
    }
}

// -------------------- f32x2 node update (K=64), fp16 Ag + Xin, fp16 out ---------
__global__ void __launch_bounds__(128) node_update64(
    const uint4* __restrict__ Agh, const uint4* __restrict__ Xh,
    const float* __restrict__ Wrel, const float* __restrict__ Wroot,
    const float* __restrict__ bias, __half* __restrict__ Outh, float* stats) {
    constexpr int PAD = 66;
    extern __shared__ float sm[];
    float* sA   = sm;
    float* sX   = sA + 64 * PAD;
    ull*   sWr  = (ull*)(sX + 64 * PAD);
    ull*   sWo  = sWr + 32 * 64;
    float* sSum = (float*)(sWo + 32 * 64);
    float* sSq  = sSum + 64;

    const int tid = threadIdx.x;
    const int base = blockIdx.x * 64;

    for (int idx = tid; idx < 32 * 16; idx += 128) {
        int k2 = idx >> 4, c4 = idx & 15;
        float4 r0 = ((const float4*)Wrel)[(2 * k2) * 16 + c4];
        float4 r1 = ((const float4*)Wrel)[(2 * k2 + 1) * 16 + c4];
        ull* p = &sWr[k2 * 64 + c4 * 4];
        p[0] = pack2(r0.x, r1.x); p[1] = pack2(r0.y, r1.y);
        p[2] = pack2(r0.z, r1.z); p[3] = pack2(r0.w, r1.w);
        r0 = ((const float4*)Wroot)[(2 * k2) * 16 + c4];
        r1 = ((const float4*)Wroot)[(2 * k2 + 1) * 16 + c4];
        p = &sWo[k2 * 64 + c4 * 4];
        p[0] = pack2(r0.x, r1.x); p[1] = pack2(r0.y, r1.y);
        p[2] = pack2(r0.z, r1.z); p[3] = pack2(r0.w, r1.w);
    }
    for (int i = tid; i < 64 * 8; i += 128) {
        int r = i >> 3, c = i & 7;
        int n = base + r;
        uint4 va = make_uint4(0u, 0u, 0u, 0u), vx = va;
        if (n < NN) {
            va = Agh[(size_t)n * 8 + c];
            vx = Xh[(size_t)n * 8 + c];
        }
        __half2* hpa = (__half2*)&va;
        __half2* hpx = (__half2*)&vx;
        float* oa = &sA[r * PAD + c * 8];
        float* ox = &sX[r * PAD + c * 8];
#pragma unroll
        for (int j = 0; j < 4; j++) {
            float2 fa = __half22float2(hpa[j]);
            float2 fx = __half22float2(hpx[j]);
            oa[2 * j] = fa.x; oa[2 * j + 1] = fa.y;
            ox[2 * j] = fx.x; ox[2 * j + 1] = fx.y;
        }
    }
    if (tid < 64) { sSum[tid] = 0.f; sSq[tid] = 0.f; }
    __syncthreads();

    const int f0 = (tid & 7) * 2;
    const int ng = (tid >> 3) * 4;

    ull acc2[4][8];
#pragma unroll
    for (int i = 0; i < 4; i++)
#pragma unroll
        for (int j = 0; j < 8; j++) acc2[i][j] = 0ull;

#pragma unroll 2
    for (int k2 = 0; k2 < 32; ++k2) {
        ull av[4], xv[4];
#pragma unroll
        for (int i = 0; i < 4; i++) {
            av[i] = *(const ull*)&sA[(ng + i) * PAD + 2 * k2];
            xv[i] = *(const ull*)&sX[(ng + i) * PAD + 2 * k2];
        }
#pragma unroll
        for (int c = 0; c < 4; c++) {
            ulonglong2 wr = *(const ulonglong2*)&sWr[k2 * 64 + f0 + 16 * c];
            ulonglong2 wo = *(const ulonglong2*)&sWo[k2 * 64 + f0 + 16 * c];
#pragma unroll
            for (int i = 0; i < 4; i++) {
                fma2(acc2[i][2 * c],     av[i], wr.x);
                fma2(acc2[i][2 * c + 1], av[i], wr.y);
                fma2(acc2[i][2 * c],     xv[i], wo.x);
                fma2(acc2[i][2 * c + 1], xv[i], wo.y);
            }
        }
    }

    float bz[8];
#pragma unroll
    for (int c = 0; c < 4; c++) {
        float2 b2 = *(const float2*)&bias[f0 + 16 * c];
        bz[2 * c] = b2.x; bz[2 * c + 1] = b2.y;
    }

    float s[8], q[8];
#pragma unroll
    for (int j = 0; j < 8; j++) { s[j] = 0.f; q[j] = 0.f; }

#pragma unroll
    for (int i = 0; i < 4; i++) {
        int n = base + ng + i;
        if (n < NN) {
#pragma unroll
            for (int c = 0; c < 4; c++) {
                float2 e0 = unpack2(acc2[i][2 * c]);
                float2 e1 = unpack2(acc2[i][2 * c + 1]);
                float o0 = e0.x + e0.y + bz[2 * c];
                float o1 = e1.x + e1.y + bz[2 * c + 1];
                __half2 hv = __floats2half2_rn(o0, o1);
                *(__half2*)&Outh[(size_t)n * 64 + f0 + 16 * c] = hv;
                s[2 * c] += o0; q[2 * c] += o0 * o0;
                s[2 * c + 1] += o1; q[2 * c + 1] += o1 * o1;
            }
        }
    }
#pragma unroll
    for (int c = 0; c < 4; c++) {
        atomicAdd(&sSum[f0 + 16 * c],     s[2 * c]);
        atomicAdd(&sSum[f0 + 16 * c + 1], s[2 * c + 1]);
        atomicAdd(&sSq[f0 + 16 * c],      q[2 * c]);
        atomicAdd(&sSq[f0 + 16 * c + 1],  q[2 * c + 1]);
    }
    __syncthreads();
    if (tid < 64) {
        atomicAdd(&stats[tid], sSum[tid]);
        atomicAdd(&stats[64 + tid], sSq[tid]);
    }
}

// -------------------- BN finalize + apply + ReLU (half2 arithmetic) -------------
__global__ void __launch_bounds__(256) bn_act_h(
    const uint4* __restrict__ inh, const float* __restrict__ stats,
    const float* __restrict__ g, const float* __restrict__ be,
    uint4* __restrict__ outh) {
    __shared__ __half2 sc2[32], sh2[32];
    if (threadIdx.x < 32) {
        int f = threadIdx.x * 2;
        const float inv = 1.f / (float)NN;
        float m0 = stats[f] * inv, m1 = stats[f + 1] * inv;
        float v0 = stats[64 + f] * inv - m0 * m0;
        float v1 = stats[64 + f + 1] * inv - m1 * m1;
        float s0 = g[f] * rsqrtf(v0 + 1e-5f);
        float s1 = g[f + 1] * rsqrtf(v1 + 1e-5f);
        sc2[threadIdx.x] = __floats2half2_rn(s0, s1);
        sh2[threadIdx.x] = __floats2half2_rn(fmaf(-m0, s0, be[f]), fmaf(-m1, s1, be[f + 1]));
    }
    __syncthreads();
    int i = blockIdx.x * blockDim.x + threadIdx.x;
    if (i >= NN * 8) return;
    int c4 = (i & 7) * 4;
    uint4 v = inh[i];
    __half2* hp = (__half2*)&v;
    const __half2 z2 = __float2half2_rn(0.f);
#pragma unroll
    for (int j = 0; j < 4; j++)
        hp[j] = __hmax2(__hfma2(hp[j], sc2[c4 + j], sh2[c4 + j]), z2);
    outh[i] = v;
}

// -------------------- layer-2 pooled GEMM + MLP head (fp16 agg, 64 thr) ---------
__global__ void pool2_head(const uint4* __restrict__ Agh, const uint4* __restrict__ Xh,
                           const float* __restrict__ W2rel, const float* __restrict__ W2root,
                           const float* __restrict__ b2, const int* __restrict__ goff,
                           const float* __restrict__ Wl1, const float* __restrict__ bl1,
                           const float* __restrict__ Wl2, const float* __restrict__ bl2,
                           float* __restrict__ out) {
    __shared__ float sAg[64], sXp[64], sPool[64], sz[64];
    int g = blockIdx.x, t = threadIdx.x;
    int beg = goff[g], end = goff[g + 1];
    const __half* ah = (const __half*)Agh;
    const __half* xh = (const __half*)Xh;
    float sa = 0.f, sx = 0.f;
    for (int n = beg; n < end; ++n) {
        sa += __half2float(ah[(size_t)n * 64 + t]);
        sx += __half2float(xh[(size_t)n * 64 + t]);
    }
    sAg[t] = sa; sXp[t] = sx;
    __syncthreads();
    float cnt = (float)(end - beg);
    float acc = cnt * b2[t];
#pragma unroll 8
    for (int k = 0; k < 64; k++)
        acc += sAg[k] * W2rel[k * 64 + t] + sXp[k] * W2root[k * 64 + t];
    sPool[t] = acc / fmaxf(cnt, 1.f);
    __syncthreads();
    float z = bl1[t];
#pragma unroll 8
    for (int k = 0; k < 64; k++) z = fmaf(sPool[k], Wl1[k * 64 + t], z);
    sz[t] = fmaxf(z, 0.f);
    __syncthreads();
    if (t < 6) {
        float o = bl2[t];
#pragma unroll 8
        for (int k = 0; k < 64; k++) o = fmaf(sz[k], Wl2[k * 6 + t], o);
        out[g * 6 + t] = o;
    }
}

// -------------------- launch --------------------
extern "C" void kernel_launch(void* const* d_in, const int* in_sizes, int n_in,
                              void* d_out, int out_size) {
    const float* x     = (const float*)d_in[0];
    const int*   ei    = (const int*)d_in[1];
    const float* ew    = (const float*)d_in[2];
    const int*   batch = (const int*)d_in[3];
    const float *Wrel0 = (const float*)d_in[4],  *Wroot0 = (const float*)d_in[5],  *b0 = (const float*)d_in[6];
    const float *Wrel1 = (const float*)d_in[7],  *Wroot1 = (const float*)d_in[8],  *b1 = (const float*)d_in[9];
    const float *Wrel2 = (const float*)d_in[10], *Wroot2 = (const float*)d_in[11], *b2 = (const float*)d_in[12];
    const float *g0 = (const float*)d_in[13], *be0 = (const float*)d_in[14];
    const float *g1 = (const float*)d_in[15], *be1 = (const float*)d_in[16];
    const float *Wl1 = (const float*)d_in[17], *bl1 = (const float*)d_in[18];
    const float *Wl2 = (const float*)d_in[19], *bl2 = (const float*)d_in[20];
    float* out = (float*)d_out;

    const int* src = ei;
    const int* dst = ei + EE;

    float *pA4, *pStats;
    uint4 *pAh, *pB, *pH, *pXh;
    int *pCnt, *pGoff;
    int2* pEpack;
    cudaGetSymbolAddress((void**)&pAh, g_Ah);
    cudaGetSymbolAddress((void**)&pA4, g_A4);
    cudaGetSymbolAddress((void**)&pB, g_B);
    cudaGetSymbolAddress((void**)&pH, g_H);
    cudaGetSymbolAddress((void**)&pXh, g_xh);
    cudaGetSymbolAddress((void**)&pStats, g_stats);
    cudaGetSymbolAddress((void**)&pCnt, g_cnt);
    cudaGetSymbolAddress((void**)&pGoff, g_goff);
    cudaGetSymbolAddress((void**)&pEpack, g_epack);

    const int smem64 = 64 * 66 * 4 * 2 + 32 * 64 * 8 * 2 + 128 * 4;       // 67072 B
    const int smem9  = (64 * 18 * 2 + 9 * 64 * 2 + 128) * (int)sizeof(float);  // 14336 B
    cudaFuncSetAttribute((const void*)node_update64,
                         cudaFuncAttributeMaxDynamicSharedMemorySize, smem64);

    const int NB = (NN + 63) / 64;

    // ---- slotted CSR build + prep (fused; memset restored) ----
    cudaMemsetAsync(pCnt, 0, NN * sizeof(int));
    place_prep<<<(EE + 511) / 512, 512>>>(src, dst, ew, pCnt, pEpack, x, pXh, batch, pGoff);

    // ---- layer 0 (fp16 input rows) ----
    agg_csr4h<<<(NN + 127) / 128, 256>>>(pXh, pCnt, pEpack, pA4, pStats);
    node_update9<<<NB, 128, smem9>>>(pA4, pXh, Wrel0, Wroot0, b0, pB, pStats);
    bn_act_h<<<(NN * 8 + 255) / 256, 256>>>(pB, pStats, g0, be0, pH);

    // ---- layer 1 ----
    agg_csr_h<<<(NN + 31) / 32, 256>>>(pH, pCnt, pEpack, pAh);
    node_update64<<<NB, 128, smem64>>>(pAh, pH, Wrel1, Wroot1, b1, (__half*)pB, pStats + 128);
    bn_act_h<<<(NN * 8 + 255) / 256, 256>>>(pB, pStats + 128, g1, be1, pH);

    // ---- layer 2 ----
    agg_csr_h<<<(NN + 31) / 32, 256>>>(pH, pCnt, pEpack, pAh);
    pool2_head<<<GG, 64>>>(pAh, pH, Wrel2, Wroot2, b2, pGoff, Wl1, bl1, Wl2, bl2, out);
}